// round 11
// baseline (speedup 1.0000x reference)
#include <cuda_runtime.h>
#include <cuda_fp16.h>
#include <stdint.h>
#include <math.h>

// Problem constants
#define BATCH 16
#define TT    1024
#define DIN   384
#define H1C   1024
#define H2C   1024
#define KW    9

// ---------------- scratch (device globals) -----------------------------------
__device__ __align__(128) __half g_inh[BATCH * TT * DIN];     // fp16 input   [b][t][384]
__device__ __align__(128) __half g_w1h[H1C * DIN];            // fp16 w1      [c][384]
__device__ __align__(128) __half g_w2h[DIN * H2C];            // fp16 w2      [d][1024]
__device__ __align__(128) __half g_pwT[BATCH * H2C * H1C];    // fp16 p_w^T   [b][o][1024]
__device__ __align__(128) __half g_xh [BATCH * TT * H1C];     // mish out     [b][t][c]
__device__ __align__(128) __half g_yh [BATCH * TT * H1C];     // conv out     [b][t][c]
__device__ __align__(128) __half g_zh [BATCH * TT * H2C];     // pointwise    [b][t][o]
__device__ float g_invnd[BATCH * KW];
__device__ float g_invnp[BATCH * H2C];
__device__ int   g_yflags[BATCH * 8];   // conv -> GEMM2 (count to 16)
__device__ int   g_pnflags[BATCH];      // pnorm -> GEMM2 (count to 128)
__device__ int   g_zflags[BATCH * 8];   // GEMM2 -> GEMM3 (count to 8)

// ---------------- helpers ----------------------------------------------------
__device__ __forceinline__ float mish_f(float v) {
    float sp = fmaxf(v, 0.f) + log1pf(expf(-fabsf(v)));
    return v * tanhf(sp);
}

__device__ __forceinline__ unsigned smem_u32(const void* p) {
    unsigned a;
    asm("{ .reg .u64 t; cvta.to.shared.u64 t, %1; cvt.u32.u64 %0, t; }" : "=r"(a) : "l"(p));
    return a;
}

__device__ __forceinline__ void cp_async16(unsigned dst, const void* src) {
    asm volatile("cp.async.cg.shared.global [%0], [%1], 16;" :: "r"(dst), "l"(src));
}

__device__ __forceinline__ void ldsm_x4(unsigned* r, unsigned addr) {
    asm volatile("ldmatrix.sync.aligned.m8n8.x4.shared.b16 {%0,%1,%2,%3}, [%4];"
        : "=r"(r[0]), "=r"(r[1]), "=r"(r[2]), "=r"(r[3]) : "r"(addr));
}

__device__ __forceinline__ void mma16816(float* d, const unsigned* a, unsigned b0, unsigned b1) {
    asm volatile("mma.sync.aligned.m16n8k16.row.col.f32.f16.f16.f32 "
        "{%0,%1,%2,%3}, {%4,%5,%6,%7}, {%8,%9}, {%0,%1,%2,%3};"
        : "+f"(d[0]), "+f"(d[1]), "+f"(d[2]), "+f"(d[3])
        : "r"(a[0]), "r"(a[1]), "r"(a[2]), "r"(a[3]), "r"(b0), "r"(b1));
}

// ---------------- mma.sync fp16 GEMM body (R9 config) ------------------------
// 256 threads, 2x4 warps on 64x32 tiles, K-chunk 32, 4-stage cp.async ring.
// MODE 1: C fp16 = mish(acc + aux1[n])
// MODE 2: C fp16 = acc*aux1[b,n] + aux2[b,n]
// MODE 3: C f32 = acc + aux1[n] + R[b][m][n]
#define PITCH   80   // bytes per 32-half smem row (64B data + 16B pad)
#define NSTAGE  4
#define OPSTR   (128 * PITCH)            // 10240 per operand per stage
#define STSTR   (2 * OPSTR)              // 20480 per stage
#define SMEM_GEMM (NSTAGE * STSTR)       // 81920

template <int MODE>
__device__ __forceinline__ void gemm_body(
    int m0, int n0, int b,
    const __half* __restrict__ A, long long sA,
    const __half* __restrict__ B, long long sB,
    void* __restrict__ Cv, long long sC,
    int Ks, int ldc,
    const float* __restrict__ aux1, int a1s,
    const float* __restrict__ aux2, int a2s,
    const float* __restrict__ R,
    unsigned char* dynsm) {
    const int tid = threadIdx.x;
    const int wid = tid >> 5, lane = tid & 31;
    const int wm = wid & 1, wn = wid >> 1;   // 2 x 4 warp grid

    const char* Ab = (const char*)(A + (long long)b * sA);
    const char* Bb = (const char*)(B + (long long)b * sB);
    const long long rowb = (long long)Ks * 2;   // fp16 row bytes

    // cp.async geometry: thread t loads row t/2, 32B at (t&1)*32
    const int lrow = tid >> 1;
    const int lcB = (tid & 1) * 32;
    const char* Agp = Ab + (long long)(m0 + lrow) * rowb + lcB;
    const char* Bgp = Bb + (long long)(n0 + lrow) * rowb + lcB;
    const unsigned smBase = smem_u32(dynsm);
    const unsigned AsD = smBase + (unsigned)(lrow * PITCH + lcB);
    const unsigned BsD = smBase + OPSTR + (unsigned)(lrow * PITCH + lcB);

    const int nch = Ks >> 5;

    float acc[4][4][4];
#pragma unroll
    for (int i = 0; i < 4; i++)
#pragma unroll
        for (int j = 0; j < 4; j++)
#pragma unroll
            for (int r = 0; r < 4; r++) acc[i][j][r] = 0.f;

    // ldmatrix lane offsets
    const unsigned aLane = (unsigned)((lane & 15) * PITCH + (lane >> 4) * 16);
    const unsigned bLane = (unsigned)(((lane & 8) + (lane & 7)) * PITCH + (lane >> 4) * 16);
    const unsigned baseA0 = smBase + (unsigned)(wm * 64 * PITCH);
    const unsigned baseB0 = smBase + OPSTR + (unsigned)(wn * 32 * PITCH);

#define ISSUE(ic) do { \
    int _o = (ic) * 64; \
    unsigned _st = (unsigned)((ic) % NSTAGE) * STSTR; \
    cp_async16(AsD + _st, Agp + _o); \
    cp_async16(AsD + _st + 16, Agp + _o + 16); \
    cp_async16(BsD + _st, Bgp + _o); \
    cp_async16(BsD + _st + 16, Bgp + _o + 16); \
    asm volatile("cp.async.commit_group;"); \
} while (0)

    // prologue: NSTAGE-1 groups always committed (empty when past end)
#pragma unroll
    for (int p = 0; p < NSTAGE - 1; p++) {
        if (p < nch) ISSUE(p);
        else asm volatile("cp.async.commit_group;");
    }

    for (int ic = 0; ic < nch; ic++) {
        asm volatile("cp.async.wait_group %0;" :: "n"(NSTAGE - 2));
        __syncthreads();
        // prefetch chunk ic+3 into the slot last read at iteration ic-1
        if (ic + NSTAGE - 1 < nch) ISSUE(ic + NSTAGE - 1);
        else asm volatile("cp.async.commit_group;");

        unsigned st = (unsigned)(ic % NSTAGE) * STSTR;
        unsigned bA = baseA0 + st, bB = baseB0 + st;
#pragma unroll
        for (int ks = 0; ks < 2; ks++) {
            unsigned afr[4][4];
#pragma unroll
            for (int mi = 0; mi < 4; mi++)
                ldsm_x4(afr[mi], bA + (unsigned)(mi * 16 * PITCH) + (unsigned)(ks * 32) + aLane);
            unsigned bfr[4][2];
#pragma unroll
            for (int nj = 0; nj < 2; nj++) {
                unsigned r[4];
                ldsm_x4(r, bB + (unsigned)(nj * 16 * PITCH) + (unsigned)(ks * 32) + bLane);
                bfr[2 * nj][0] = r[0]; bfr[2 * nj][1] = r[2];
                bfr[2 * nj + 1][0] = r[1]; bfr[2 * nj + 1][1] = r[3];
            }
#pragma unroll
            for (int mi = 0; mi < 4; mi++)
#pragma unroll
                for (int ni = 0; ni < 4; ni++)
                    mma16816(acc[mi][ni], afr[mi], bfr[ni][0], bfr[ni][1]);
        }
    }
#undef ISSUE

    // epilogue: rows quad, quad+8; cols 2*(lane&3)+{0,1}
    const int quad = lane >> 2;
    const int col2 = (lane & 3) * 2;
#pragma unroll
    for (int mi = 0; mi < 4; mi++) {
#pragma unroll
        for (int half = 0; half < 2; half++) {
            int m = m0 + wm * 64 + mi * 16 + quad + half * 8;
#pragma unroll
            for (int ni = 0; ni < 4; ni++) {
                int n = n0 + wn * 32 + ni * 8 + col2;
                float v0 = acc[mi][ni][2 * half];
                float v1 = acc[mi][ni][2 * half + 1];
                if (MODE == 1) {
                    v0 = mish_f(v0 + aux1[n]);
                    v1 = mish_f(v1 + aux1[n + 1]);
                    __half* C = (__half*)Cv + (long long)b * sC + (long long)m * ldc + n;
                    *(__half2*)C = __floats2half2_rn(v0, v1);
                } else if (MODE == 2) {
                    v0 = v0 * aux1[b * a1s + n] + aux2[b * a2s + n];
                    v1 = v1 * aux1[b * a1s + n + 1] + aux2[b * a2s + n + 1];
                    __half* C = (__half*)Cv + (long long)b * sC + (long long)m * ldc + n;
                    *(__half2*)C = __floats2half2_rn(v0, v1);
                } else {
                    long long off = (long long)b * sC + (long long)m * ldc + n;
                    v0 = v0 + aux1[n] + R[off];
                    v1 = v1 + aux1[n + 1] + R[off + 1];
                    *(float2*)((float*)Cv + off) = make_float2(v0, v1);
                }
            }
        }
    }
}

// ---------------- prep: cvt input/w1/w2 + dnorm + flag reset, one launch -----
__global__ void prep_kernel(const float* __restrict__ input, const float* __restrict__ w1_w,
                            const float* __restrict__ w2_w, const float* __restrict__ d_w,
                            __half* __restrict__ inh, __half* __restrict__ w1h,
                            __half* __restrict__ w2h, float* __restrict__ invnd,
                            int* __restrict__ yflags, int* __restrict__ pnflags,
                            int* __restrict__ zflags) {
    int bx = blockIdx.x;
    int tid = threadIdx.x;
    if (bx < 6912) {
        const float4* src;
        uint2* dst;
        long long i;
        if (bx < 6144) {
            src = (const float4*)input; dst = (uint2*)inh;
            i = (long long)bx * 256 + tid;
        } else if (bx < 6528) {
            src = (const float4*)w1_w; dst = (uint2*)w1h;
            i = (long long)(bx - 6144) * 256 + tid;
        } else {
            src = (const float4*)w2_w; dst = (uint2*)w2h;
            i = (long long)(bx - 6528) * 256 + tid;
        }
        float4 v = src[i];
        __half2 a = __floats2half2_rn(v.x, v.y);
        __half2 b = __floats2half2_rn(v.z, v.w);
        dst[i] = make_uint2(*(unsigned*)&a, *(unsigned*)&b);
    } else if (bx < 6930) {
        // dnorm: warp per (b,k), 18 blocks x 8 warps = 144
        int w = (bx - 6912) * 8 + (tid >> 5);
        int lane = tid & 31;
        int b = w / KW, k = w - KW * b;
        float s = 0.f;
#pragma unroll 8
        for (int c = lane; c < H1C; c += 32) {
            float v = d_w[((long long)b * H1C + c) * KW + k];
            s += v * v;
        }
#pragma unroll
        for (int o = 16; o > 0; o >>= 1) s += __shfl_xor_sync(0xffffffffu, s, o);
        if (lane == 0) invnd[b * KW + k] = 1.f / fmaxf(sqrtf(s), 1e-12f);
    } else {
        if (tid < BATCH * 8) { yflags[tid] = 0; zflags[tid] = 0; }
        if (tid < BATCH) pnflags[tid] = 0;
    }
}

// ---------------- fused GEMM1 + p_w transpose --------------------------------
// blocks [0,1024): GEMM1 tiles | [1024,5120): tsplit 64x64 tiles
__global__ void __launch_bounds__(256, 2)
gemm1_tsplit(const __half* __restrict__ A, const __half* __restrict__ Bw,
             __half* __restrict__ X, const float* __restrict__ w1b,
             const float* __restrict__ pw, __half* __restrict__ pwT) {
    extern __shared__ __align__(16) unsigned char dynsm[];
    int bx = blockIdx.x;
    int tid = threadIdx.x;
    if (bx < 1024) {
        int b = bx >> 6;
        int rem = bx & 63;
        int m0 = (rem >> 3) * 128, n0 = (rem & 7) * 128;
        gemm_body<1>(m0, n0, b, A, (long long)TT * DIN, Bw, 0,
                     (void*)X, (long long)TT * H1C, DIN, H1C,
                     w1b, 0, nullptr, 0, nullptr, dynsm);
    } else {
        // tsplit: [b][c][o] f32 -> [b][o][c] fp16, 64x64 tiles
        int lin = bx - 1024;
        int b = lin >> 8;
        int rem = lin & 255;
        int c0 = (rem >> 4) * 64;
        int o0 = (rem & 15) * 64;
        float(*tile)[65] = (float(*)[65])dynsm;
        const float* I = pw + (long long)b * H1C * H2C;
        __half* O = pwT + (long long)b * H2C * H1C;
        int tx = tid & 15, ty = tid >> 4;  // 16 x 16
#pragma unroll
        for (int it = 0; it < 4; it++) {
            int r = ty + it * 16;
            float4 v = *(const float4*)(I + (long long)(c0 + r) * H2C + o0 + tx * 4);
            tile[r][tx * 4] = v.x;
            tile[r][tx * 4 + 1] = v.y;
            tile[r][tx * 4 + 2] = v.z;
            tile[r][tx * 4 + 3] = v.w;
        }
        __syncthreads();
        int wid = tid >> 5, lane = tid & 31;
#pragma unroll
        for (int o = wid; o < 64; o += 8) {
            __half2 v = __floats2half2_rn(tile[2 * lane][o], tile[2 * lane + 1][o]);
            *(__half2*)(O + (long long)(o0 + o) * H1C + c0 + 2 * lane) = v;
        }
    }
}

// ---------------- mega relay: conv + pnorm -> GEMM2 -> GEMM3 -----------------
// bids [0,2048): dwconv producers  (arrive yflags[b*8 + t0/128], 16 per tile)
// bids [2048,4096): pnorm producers (arrive pnflags[b], 128 per batch)
// bids [4096,5120): GEMM2 tiles (wait yflags==16 && pnflags==128; arrive zflags)
// bids [5120,5504): GEMM3 tiles (wait zflags==8)
__global__ void __launch_bounds__(256, 2)
convgemm23(const __half* __restrict__ x, __half* __restrict__ y,
           const float* __restrict__ d_w, const float* __restrict__ d_g,
           const float* __restrict__ d_b, const float* __restrict__ p_g,
           const float* __restrict__ invnd,
           const __half* __restrict__ pwT, float* __restrict__ invnp,
           __half* __restrict__ z, const float* __restrict__ pb,
           const __half* __restrict__ w2h, float* __restrict__ out,
           const float* __restrict__ w2b, const float* __restrict__ resid,
           int* __restrict__ yflags, int* __restrict__ pnflags,
           int* __restrict__ zflags) {
    extern __shared__ __align__(16) unsigned char dynsm[];
    int bid = blockIdx.x;
    int tid = threadIdx.x;  // 256
    if (bid < 2048) {
        // depthwise conv block (dynamic smem)
        int b = bid >> 7;
        int rem = bid & 127;
        int c0 = (rem & 7) * 128;
        int t0 = (rem >> 3) * 64;
        float* xs = (float*)dynsm;            // [72][128]
        float* ws = xs + 72 * 128;            // [KW][128]
        float* sdb = ws + KW * 128;           // [128]
        float* spg = sdb + 128;               // [128]
        const __half* xb = x + (long long)b * TT * H1C;
        for (int i = tid; i < 72 * 64; i += 256) {
            int r = i >> 6, c2 = i & 63;
            int t = t0 - 4 + r;
            float2 v = make_float2(0.f, 0.f);
            if (t >= 0 && t < TT)
                v = __half22float2(*(const __half2*)(xb + (long long)t * H1C + c0 + 2 * c2));
            xs[r * 128 + 2 * c2] = v.x;
            xs[r * 128 + 2 * c2 + 1] = v.y;
        }
        if (tid < 128) {
            int c = c0 + tid;
            float g = d_g[b * H1C + c];
#pragma unroll
            for (int k = 0; k < KW; k++)
                ws[k * 128 + tid] = d_w[((long long)b * H1C + c) * KW + k] * invnd[b * KW + k] * g;
            sdb[tid] = d_b[b * H1C + c];
            spg[tid] = p_g[b * H1C + c];
        }
        __syncthreads();
        int tx = tid & 127, ty = tid >> 7;
        float w9[KW];
#pragma unroll
        for (int k = 0; k < KW; k++) w9[k] = ws[k * 128 + tx];
        float db = sdb[tx], pg = spg[tx];
        __half* yb = y + (long long)b * TT * H1C;
#pragma unroll 4
        for (int q = 0; q < 32; q++) {
            int tt = ty * 32 + q;
            float a = 0.f;
#pragma unroll
            for (int k = 0; k < KW; k++) a = fmaf(xs[(tt + k) * 128 + tx], w9[k], a);
            float v = (a * (float)TT + db) * pg;
            yb[(long long)(t0 + tt) * H1C + c0 + tx] = __float2half(v);
        }
        __syncthreads();
        if (tid == 0) {
            __threadfence();
            atomicAdd(&yflags[b * 8 + (t0 >> 7)], 1);
        }
    } else if (bid < 4096) {
        // pnorm: 8 warps, one (b,o) row each; all rows share b
        int lin = bid - 2048;
        int row = lin * 8 + (tid >> 5);
        int lane = tid & 31;
        const __half2* p = (const __half2*)(pwT + (long long)row * H1C);
        float s = 0.f;
#pragma unroll 4
        for (int j = lane; j < H1C / 2; j += 32) {
            float2 v = __half22float2(p[j]);
            s += v.x * v.x + v.y * v.y;
        }
#pragma unroll
        for (int o = 16; o > 0; o >>= 1) s += __shfl_xor_sync(0xffffffffu, s, o);
        if (lane == 0) invnp[row] = 1.f / fmaxf(sqrtf(s), 1e-12f);
        __syncthreads();
        if (tid == 0) {
            __threadfence();
            atomicAdd(&pnflags[row >> 10], 1);
        }
    } else if (bid < 5120) {
        // GEMM2 tile
        int lin = bid - 4096;
        int b = lin >> 6, my = (lin >> 3) & 7, nx = lin & 7;
        if (tid == 0) {
            volatile int* fy = &yflags[b * 8 + my];
            while (*fy < 16) {}
            volatile int* fp = &pnflags[b];
            while (*fp < 128) {}
        }
        __syncthreads();
        gemm_body<2>(my * 128, nx * 128, b,
                     y, (long long)TT * H1C, pwT, (long long)H2C * H1C,
                     (void*)z, (long long)TT * H2C, H1C, H2C,
                     invnp, H2C, pb, H2C, nullptr, dynsm);
        __syncthreads();
        if (tid == 0) {
            __threadfence();
            atomicAdd(&zflags[b * 8 + my], 1);
        }
    } else {
        // GEMM3 tile
        int lin = bid - 5120;
        int b = lin / 24;
        int rem = lin - b * 24;
        int my = rem / 3, dx = rem - my * 3;
        if (tid == 0) {
            volatile int* f = &zflags[b * 8 + my];
            while (*f < 8) {}
        }
        __syncthreads();
        gemm_body<3>(my * 128, dx * 128, b,
                     z, (long long)TT * H2C, w2h, 0,
                     (void*)out, (long long)TT * DIN, H2C, DIN,
                     w2b, 0, nullptr, 0, resid, dynsm);
    }
}

// ---------------- launch ------------------------------------------------------
extern "C" void kernel_launch(void* const* d_in, const int* in_sizes, int n_in,
                              void* d_out, int out_size) {
    const float* input = (const float*)d_in[0];
    const float* d_w   = (const float*)d_in[1];
    const float* d_g   = (const float*)d_in[2];
    const float* d_b   = (const float*)d_in[3];
    const float* p_w   = (const float*)d_in[4];
    const float* p_g   = (const float*)d_in[5];
    const float* p_b   = (const float*)d_in[6];
    const float* w1_w  = (const float*)d_in[7];
    const float* w1_b  = (const float*)d_in[8];
    const float* w2_w  = (const float*)d_in[9];
    const float* w2_b  = (const float*)d_in[10];
    float* out = (float*)d_out;
    (void)in_sizes; (void)n_in; (void)out_size;

    __half *p_inh, *p_w1h, *p_w2h, *p_pwT, *p_xh, *p_yh, *p_zh;
    float *p_invnd, *p_invnp;
    int *p_yflags, *p_pnflags, *p_zflags;
    cudaGetSymbolAddress((void**)&p_inh, g_inh);
    cudaGetSymbolAddress((void**)&p_w1h, g_w1h);
    cudaGetSymbolAddress((void**)&p_w2h, g_w2h);
    cudaGetSymbolAddress((void**)&p_pwT, g_pwT);
    cudaGetSymbolAddress((void**)&p_xh, g_xh);
    cudaGetSymbolAddress((void**)&p_yh, g_yh);
    cudaGetSymbolAddress((void**)&p_zh, g_zh);
    cudaGetSymbolAddress((void**)&p_invnd, g_invnd);
    cudaGetSymbolAddress((void**)&p_invnp, g_invnp);
    cudaGetSymbolAddress((void**)&p_yflags, g_yflags);
    cudaGetSymbolAddress((void**)&p_pnflags, g_pnflags);
    cudaGetSymbolAddress((void**)&p_zflags, g_zflags);

    // opt-in to 80KB dynamic smem (idempotent)
    cudaFuncSetAttribute(gemm1_tsplit, cudaFuncAttributeMaxDynamicSharedMemorySize, SMEM_GEMM);
    cudaFuncSetAttribute(convgemm23, cudaFuncAttributeMaxDynamicSharedMemorySize, SMEM_GEMM);

    // 1) prep: all fp16 conversions + dnorm + relay-flag reset
    prep_kernel<<<6931, 256>>>(input, w1_w, w2_w, d_w, p_inh, p_w1h, p_w2h, p_invnd,
                               p_yflags, p_pnflags, p_zflags);

    // 2) GEMM1 (mish) fused with p_w transpose
    gemm1_tsplit<<<1024 + 4096, 256, SMEM_GEMM>>>(p_inh, p_w1h, p_xh, w1_b, p_w, p_pwT);

    // 3) conv + pnorm -> GEMM2 -> GEMM3 mega relay (single launch)
    convgemm23<<<5504, 256, SMEM_GEMM>>>(p_xh, p_yh, d_w, d_g, d_b, p_g, p_invnd,
                                         p_pwT, p_invnp, p_zh, p_b,
                                         p_w2h, out, w2_b, input,
                                         p_yflags, p_pnflags, p_zflags);
}

// round 12
// speedup vs baseline: 1.1420x; 1.1420x over previous
#include <cuda_runtime.h>
#include <cuda_fp16.h>
#include <stdint.h>
#include <math.h>

// Problem constants
#define BATCH 16
#define TT    1024
#define DIN   384
#define H1C   1024
#define H2C   1024
#define KW    9

// ---------------- scratch (device globals) -----------------------------------
__device__ __align__(128) __half g_inh[BATCH * TT * DIN];     // fp16 input   [b][t][384]
__device__ __align__(128) __half g_w1h[H1C * DIN];            // fp16 w1      [c][384]
__device__ __align__(128) __half g_w2h[DIN * H2C];            // fp16 w2      [d][1024]
__device__ __align__(128) __half g_pwT[BATCH * H2C * H1C];    // fp16 p_w^T   [b][o][1024]
__device__ __align__(128) __half g_xh [BATCH * TT * H1C];     // mish out     [b][t][c]
__device__ __align__(128) __half g_yh [BATCH * TT * H1C];     // conv out     [b][t][c]
__device__ __align__(128) __half g_zh [BATCH * TT * H2C];     // pointwise    [b][t][o]
__device__ float g_invnd[BATCH * KW];
__device__ float g_invnp[BATCH * H2C];
__device__ int   g_flags[BATCH * 8];                          // relay flags (b, t-tile)

// ---------------- helpers ----------------------------------------------------
__device__ __forceinline__ float mish_f(float v) {
    float sp = fmaxf(v, 0.f) + log1pf(expf(-fabsf(v)));
    return v * tanhf(sp);
}

__device__ __forceinline__ unsigned smem_u32(const void* p) {
    unsigned a;
    asm("{ .reg .u64 t; cvta.to.shared.u64 t, %1; cvt.u32.u64 %0, t; }" : "=r"(a) : "l"(p));
    return a;
}

__device__ __forceinline__ void cp_async16(unsigned dst, const void* src) {
    asm volatile("cp.async.cg.shared.global [%0], [%1], 16;" :: "r"(dst), "l"(src));
}

__device__ __forceinline__ void ldsm_x4(unsigned* r, unsigned addr) {
    asm volatile("ldmatrix.sync.aligned.m8n8.x4.shared.b16 {%0,%1,%2,%3}, [%4];"
        : "=r"(r[0]), "=r"(r[1]), "=r"(r[2]), "=r"(r[3]) : "r"(addr));
}

__device__ __forceinline__ void mma16816(float* d, const unsigned* a, unsigned b0, unsigned b1) {
    asm volatile("mma.sync.aligned.m16n8k16.row.col.f32.f16.f16.f32 "
        "{%0,%1,%2,%3}, {%4,%5,%6,%7}, {%8,%9}, {%0,%1,%2,%3};"
        : "+f"(d[0]), "+f"(d[1]), "+f"(d[2]), "+f"(d[3])
        : "r"(a[0]), "r"(a[1]), "r"(a[2]), "r"(a[3]), "r"(b0), "r"(b1));
}

// ---------------- mma.sync fp16 GEMM body ------------------------------------
// 256 threads, 2x4 warps on 64x32 tiles, K-chunk 32, 5-stage cp.async ring.
// MODE 1: C fp16 = mish(acc + aux1[n])
// MODE 2: C fp16 = acc*aux1[b,n] + aux2[b,n]
// MODE 3: C f32 = acc + aux1[n] + R[b][m][n]
#define PITCH   80   // bytes per 32-half smem row (64B data + 16B pad)
#define NSTAGE  5
#define OPSTR   (128 * PITCH)            // 10240 per operand per stage
#define STSTR   (2 * OPSTR)              // 20480 per stage
#define SMEM_GEMM (NSTAGE * STSTR)       // 102400

template <int MODE>
__device__ __forceinline__ void gemm_body(
    int m0, int n0, int b,
    const __half* __restrict__ A, long long sA,
    const __half* __restrict__ B, long long sB,
    void* __restrict__ Cv, long long sC,
    int Ks, int ldc,
    const float* __restrict__ aux1, int a1s,
    const float* __restrict__ aux2, int a2s,
    const float* __restrict__ R,
    unsigned char* dynsm) {
    const int tid = threadIdx.x;
    const int wid = tid >> 5, lane = tid & 31;
    const int wm = wid & 1, wn = wid >> 1;   // 2 x 4 warp grid

    const char* Ab = (const char*)(A + (long long)b * sA);
    const char* Bb = (const char*)(B + (long long)b * sB);
    const long long rowb = (long long)Ks * 2;   // fp16 row bytes

    // cp.async geometry: thread t loads row t/2, 32B at (t&1)*32
    const int lrow = tid >> 1;
    const int lcB = (tid & 1) * 32;
    const char* Agp = Ab + (long long)(m0 + lrow) * rowb + lcB;
    const char* Bgp = Bb + (long long)(n0 + lrow) * rowb + lcB;
    const unsigned smBase = smem_u32(dynsm);
    const unsigned AsD = smBase + (unsigned)(lrow * PITCH + lcB);
    const unsigned BsD = smBase + OPSTR + (unsigned)(lrow * PITCH + lcB);

    const int nch = Ks >> 5;

    float acc[4][4][4];
#pragma unroll
    for (int i = 0; i < 4; i++)
#pragma unroll
        for (int j = 0; j < 4; j++)
#pragma unroll
            for (int r = 0; r < 4; r++) acc[i][j][r] = 0.f;

    // ldmatrix lane offsets
    const unsigned aLane = (unsigned)((lane & 15) * PITCH + (lane >> 4) * 16);
    const unsigned bLane = (unsigned)(((lane & 8) + (lane & 7)) * PITCH + (lane >> 4) * 16);
    const unsigned baseA0 = smBase + (unsigned)(wm * 64 * PITCH);
    const unsigned baseB0 = smBase + OPSTR + (unsigned)(wn * 32 * PITCH);

#define ISSUE(ic) do { \
    int _o = (ic) * 64; \
    unsigned _st = (unsigned)((ic) % NSTAGE) * STSTR; \
    cp_async16(AsD + _st, Agp + _o); \
    cp_async16(AsD + _st + 16, Agp + _o + 16); \
    cp_async16(BsD + _st, Bgp + _o); \
    cp_async16(BsD + _st + 16, Bgp + _o + 16); \
    asm volatile("cp.async.commit_group;"); \
} while (0)

    // prologue: NSTAGE-1 groups always committed (empty when past end)
#pragma unroll
    for (int p = 0; p < NSTAGE - 1; p++) {
        if (p < nch) ISSUE(p);
        else asm volatile("cp.async.commit_group;");
    }

    for (int ic = 0; ic < nch; ic++) {
        asm volatile("cp.async.wait_group %0;" :: "n"(NSTAGE - 2));
        __syncthreads();
        // prefetch chunk ic+NSTAGE-1 into the slot last read at iteration ic-1
        if (ic + NSTAGE - 1 < nch) ISSUE(ic + NSTAGE - 1);
        else asm volatile("cp.async.commit_group;");

        unsigned st = (unsigned)(ic % NSTAGE) * STSTR;
        unsigned bA = baseA0 + st, bB = baseB0 + st;
#pragma unroll
        for (int ks = 0; ks < 2; ks++) {
            unsigned afr[4][4];
#pragma unroll
            for (int mi = 0; mi < 4; mi++)
                ldsm_x4(afr[mi], bA + (unsigned)(mi * 16 * PITCH) + (unsigned)(ks * 32) + aLane);
            unsigned bfr[4][2];
#pragma unroll
            for (int nj = 0; nj < 2; nj++) {
                unsigned r[4];
                ldsm_x4(r, bB + (unsigned)(nj * 16 * PITCH) + (unsigned)(ks * 32) + bLane);
                bfr[2 * nj][0] = r[0]; bfr[2 * nj][1] = r[2];
                bfr[2 * nj + 1][0] = r[1]; bfr[2 * nj + 1][1] = r[3];
            }
#pragma unroll
            for (int mi = 0; mi < 4; mi++)
#pragma unroll
                for (int ni = 0; ni < 4; ni++)
                    mma16816(acc[mi][ni], afr[mi], bfr[ni][0], bfr[ni][1]);
        }
    }
#undef ISSUE

    // epilogue: rows quad, quad+8; cols 2*(lane&3)+{0,1}
    const int quad = lane >> 2;
    const int col2 = (lane & 3) * 2;
#pragma unroll
    for (int mi = 0; mi < 4; mi++) {
#pragma unroll
        for (int half = 0; half < 2; half++) {
            int m = m0 + wm * 64 + mi * 16 + quad + half * 8;
#pragma unroll
            for (int ni = 0; ni < 4; ni++) {
                int n = n0 + wn * 32 + ni * 8 + col2;
                float v0 = acc[mi][ni][2 * half];
                float v1 = acc[mi][ni][2 * half + 1];
                if (MODE == 1) {
                    v0 = mish_f(v0 + aux1[n]);
                    v1 = mish_f(v1 + aux1[n + 1]);
                    __half* C = (__half*)Cv + (long long)b * sC + (long long)m * ldc + n;
                    *(__half2*)C = __floats2half2_rn(v0, v1);
                } else if (MODE == 2) {
                    v0 = v0 * aux1[b * a1s + n] + aux2[b * a2s + n];
                    v1 = v1 * aux1[b * a1s + n + 1] + aux2[b * a2s + n + 1];
                    __half* C = (__half*)Cv + (long long)b * sC + (long long)m * ldc + n;
                    *(__half2*)C = __floats2half2_rn(v0, v1);
                } else {
                    long long off = (long long)b * sC + (long long)m * ldc + n;
                    v0 = v0 + aux1[n] + R[off];
                    v1 = v1 + aux1[n + 1] + R[off + 1];
                    *(float2*)((float*)Cv + off) = make_float2(v0, v1);
                }
            }
        }
    }
}

// ---------------- prep: cvt input/w1/w2 + dnorm + flag reset, one launch -----
// blocks: [0,6144) input cvt | [6144,6528) w1 | [6528,6912) w2 | [6912,6930) dnorm
//         | 6930: zero relay flags
__global__ void prep_kernel(const float* __restrict__ input, const float* __restrict__ w1_w,
                            const float* __restrict__ w2_w, const float* __restrict__ d_w,
                            __half* __restrict__ inh, __half* __restrict__ w1h,
                            __half* __restrict__ w2h, float* __restrict__ invnd,
                            int* __restrict__ flags) {
    int bx = blockIdx.x;
    int tid = threadIdx.x;
    if (bx < 6912) {
        const float4* src;
        uint2* dst;
        long long i;
        if (bx < 6144) {
            src = (const float4*)input; dst = (uint2*)inh;
            i = (long long)bx * 256 + tid;
        } else if (bx < 6528) {
            src = (const float4*)w1_w; dst = (uint2*)w1h;
            i = (long long)(bx - 6144) * 256 + tid;
        } else {
            src = (const float4*)w2_w; dst = (uint2*)w2h;
            i = (long long)(bx - 6528) * 256 + tid;
        }
        float4 v = src[i];
        __half2 a = __floats2half2_rn(v.x, v.y);
        __half2 b = __floats2half2_rn(v.z, v.w);
        dst[i] = make_uint2(*(unsigned*)&a, *(unsigned*)&b);
    } else if (bx < 6930) {
        // dnorm: warp per (b,k), 18 blocks x 8 warps = 144
        int w = (bx - 6912) * 8 + (tid >> 5);
        int lane = tid & 31;
        int b = w / KW, k = w - KW * b;
        float s = 0.f;
#pragma unroll 8
        for (int c = lane; c < H1C; c += 32) {
            float v = d_w[((long long)b * H1C + c) * KW + k];
            s += v * v;
        }
#pragma unroll
        for (int o = 16; o > 0; o >>= 1) s += __shfl_xor_sync(0xffffffffu, s, o);
        if (lane == 0) invnd[b * KW + k] = 1.f / fmaxf(sqrtf(s), 1e-12f);
    } else {
        if (tid < BATCH * 8) flags[tid] = 0;
    }
}

// ---------------- fused GEMM1 + p_w transpose --------------------------------
// blocks [0,1024): GEMM1 tiles | [1024,5120): tsplit 64x64 tiles
__global__ void __launch_bounds__(256, 2)
gemm1_tsplit(const __half* __restrict__ A, const __half* __restrict__ Bw,
             __half* __restrict__ X, const float* __restrict__ w1b,
             const float* __restrict__ pw, __half* __restrict__ pwT) {
    extern __shared__ __align__(16) unsigned char dynsm[];
    int bx = blockIdx.x;
    int tid = threadIdx.x;
    if (bx < 1024) {
        int b = bx >> 6;
        int rem = bx & 63;
        int m0 = (rem >> 3) * 128, n0 = (rem & 7) * 128;
        gemm_body<1>(m0, n0, b, A, (long long)TT * DIN, Bw, 0,
                     (void*)X, (long long)TT * H1C, DIN, H1C,
                     w1b, 0, nullptr, 0, nullptr, dynsm);
    } else {
        // tsplit: [b][c][o] f32 -> [b][o][c] fp16, 64x64 tiles
        int lin = bx - 1024;
        int b = lin >> 8;
        int rem = lin & 255;
        int c0 = (rem >> 4) * 64;
        int o0 = (rem & 15) * 64;
        float(*tile)[65] = (float(*)[65])dynsm;
        const float* I = pw + (long long)b * H1C * H2C;
        __half* O = pwT + (long long)b * H2C * H1C;
        int tx = tid & 15, ty = tid >> 4;  // 16 x 16
#pragma unroll
        for (int it = 0; it < 4; it++) {
            int r = ty + it * 16;
            float4 v = *(const float4*)(I + (long long)(c0 + r) * H2C + o0 + tx * 4);
            tile[r][tx * 4] = v.x;
            tile[r][tx * 4 + 1] = v.y;
            tile[r][tx * 4 + 2] = v.z;
            tile[r][tx * 4 + 3] = v.w;
        }
        __syncthreads();
        int wid = tid >> 5, lane = tid & 31;
#pragma unroll
        for (int o = wid; o < 64; o += 8) {
            __half2 v = __floats2half2_rn(tile[2 * lane][o], tile[2 * lane + 1][o]);
            *(__half2*)(O + (long long)(o0 + o) * H1C + c0 + 2 * lane) = v;
        }
    }
}

// ---------------- fused depthwise conv + pnorm -------------------------------
// blocks [0,2048): dwconv (sliding-window, 1 LDS/output) | [2048,4096): pnorm
__global__ void dwconv_pnorm(const __half* __restrict__ x, __half* __restrict__ y,
                             const float* __restrict__ d_w, const float* __restrict__ d_g,
                             const float* __restrict__ d_b, const float* __restrict__ p_g,
                             const float* __restrict__ invnd,
                             const __half* __restrict__ pwT, float* __restrict__ invnp) {
    int bx = blockIdx.x;
    int tid = threadIdx.x;  // 256
    if (bx < 2048) {
        int b = bx >> 7;
        int rem = bx & 127;
        int c0 = (rem & 7) * 128;
        int t0 = (rem >> 3) * 64;
        __shared__ float xs[72][128];
        __shared__ float ws[KW][128];
        __shared__ float sdb[128], spg[128];
        const __half* xb = x + (long long)b * TT * H1C;
        for (int i = tid; i < 72 * 64; i += 256) {
            int r = i >> 6, c2 = i & 63;
            int t = t0 - 4 + r;
            float2 v = make_float2(0.f, 0.f);
            if (t >= 0 && t < TT)
                v = __half22float2(*(const __half2*)(xb + (long long)t * H1C + c0 + 2 * c2));
            xs[r][2 * c2] = v.x;
            xs[r][2 * c2 + 1] = v.y;
        }
        if (tid < 128) {
            int c = c0 + tid;
            float g = d_g[b * H1C + c];
#pragma unroll
            for (int k = 0; k < KW; k++)
                ws[k][tid] = d_w[((long long)b * H1C + c) * KW + k] * invnd[b * KW + k] * g;
            sdb[tid] = d_b[b * H1C + c];
            spg[tid] = p_g[b * H1C + c];
        }
        __syncthreads();
        int tx = tid & 127, ty = tid >> 7;
        float w9[KW];
#pragma unroll
        for (int k = 0; k < KW; k++) w9[k] = ws[k][tx];
        float db = sdb[tx], pg = spg[tx];
        __half* yb = y + (long long)b * TT * H1C;
        // sliding 9-tap window: 1 LDS per output instead of 9
        float win[KW];
#pragma unroll
        for (int k = 0; k < KW - 1; k++) win[k] = xs[ty * 32 + k][tx];
#pragma unroll
        for (int q = 0; q < 32; q++) {
            int tt = ty * 32 + q;
            win[KW - 1] = xs[tt + KW - 1][tx];
            float a = 0.f;
#pragma unroll
            for (int k = 0; k < KW; k++) a = fmaf(win[k], w9[k], a);
            float v = (a * (float)TT + db) * pg;
            yb[(long long)(t0 + tt) * H1C + c0 + tx] = __float2half(v);
#pragma unroll
            for (int k = 0; k < KW - 1; k++) win[k] = win[k + 1];
        }
    } else {
        int row = (bx - 2048) * 8 + (tid >> 5);
        int lane = tid & 31;
        const __half2* p = (const __half2*)(pwT + (long long)row * H1C);
        float s = 0.f;
#pragma unroll 4
        for (int j = lane; j < H1C / 2; j += 32) {
            float2 v = __half22float2(p[j]);
            s += v.x * v.x + v.y * v.y;
        }
#pragma unroll
        for (int o = 16; o > 0; o >>= 1) s += __shfl_xor_sync(0xffffffffu, s, o);
        if (lane == 0) invnp[row] = 1.f / fmaxf(sqrtf(s), 1e-12f);
    }
}

// ---------------- fused GEMM2 -> GEMM3 relay ---------------------------------
// bids [0,1024): GEMM2 tiles (arrive on flag[b*8+mtile] when z tile stored)
// bids [1024,1408): GEMM3 tiles (spin until flag[b*8+mtile]==8, then run)
__global__ void __launch_bounds__(256, 2)
gemm23(const __half* __restrict__ y, const __half* __restrict__ pwT,
       __half* __restrict__ z, const float* __restrict__ invnp,
       const float* __restrict__ pb,
       const __half* __restrict__ w2h, float* __restrict__ out,
       const float* __restrict__ w2b, const float* __restrict__ resid,
       int* __restrict__ flags) {
    extern __shared__ __align__(16) unsigned char dynsm[];
    int bid = blockIdx.x;
    int tid = threadIdx.x;
    if (bid < 1024) {
        int b = bid >> 6, my = (bid >> 3) & 7, nx = bid & 7;
        gemm_body<2>(my * 128, nx * 128, b,
                     y, (long long)TT * H1C, pwT, (long long)H2C * H1C,
                     (void*)z, (long long)TT * H2C, H1C, H2C,
                     invnp, H2C, pb, H2C, nullptr, dynsm);
        __syncthreads();
        if (tid == 0) {
            __threadfence();
            atomicAdd(&flags[b * 8 + my], 1);
        }
    } else {
        int lin = bid - 1024;
        int b = lin / 24;
        int rem = lin - b * 24;
        int my = rem / 3, dx = rem - my * 3;
        if (tid == 0) {
            volatile int* f = &flags[b * 8 + my];
            while (*f < 8) {}
        }
        __syncthreads();
        gemm_body<3>(my * 128, dx * 128, b,
                     z, (long long)TT * H2C, w2h, 0,
                     (void*)out, (long long)TT * DIN, H2C, DIN,
                     w2b, 0, nullptr, 0, resid, dynsm);
    }
}

// ---------------- launch ------------------------------------------------------
extern "C" void kernel_launch(void* const* d_in, const int* in_sizes, int n_in,
                              void* d_out, int out_size) {
    const float* input = (const float*)d_in[0];
    const float* d_w   = (const float*)d_in[1];
    const float* d_g   = (const float*)d_in[2];
    const float* d_b   = (const float*)d_in[3];
    const float* p_w   = (const float*)d_in[4];
    const float* p_g   = (const float*)d_in[5];
    const float* p_b   = (const float*)d_in[6];
    const float* w1_w  = (const float*)d_in[7];
    const float* w1_b  = (const float*)d_in[8];
    const float* w2_w  = (const float*)d_in[9];
    const float* w2_b  = (const float*)d_in[10];
    float* out = (float*)d_out;
    (void)in_sizes; (void)n_in; (void)out_size;

    __half *p_inh, *p_w1h, *p_w2h, *p_pwT, *p_xh, *p_yh, *p_zh;
    float *p_invnd, *p_invnp;
    int* p_flags;
    cudaGetSymbolAddress((void**)&p_inh, g_inh);
    cudaGetSymbolAddress((void**)&p_w1h, g_w1h);
    cudaGetSymbolAddress((void**)&p_w2h, g_w2h);
    cudaGetSymbolAddress((void**)&p_pwT, g_pwT);
    cudaGetSymbolAddress((void**)&p_xh, g_xh);
    cudaGetSymbolAddress((void**)&p_yh, g_yh);
    cudaGetSymbolAddress((void**)&p_zh, g_zh);
    cudaGetSymbolAddress((void**)&p_invnd, g_invnd);
    cudaGetSymbolAddress((void**)&p_invnp, g_invnp);
    cudaGetSymbolAddress((void**)&p_flags, g_flags);

    // opt-in to 100KB dynamic smem (idempotent)
    cudaFuncSetAttribute(gemm1_tsplit, cudaFuncAttributeMaxDynamicSharedMemorySize, SMEM_GEMM);
    cudaFuncSetAttribute(gemm23, cudaFuncAttributeMaxDynamicSharedMemorySize, SMEM_GEMM);

    // 1) prep: all fp16 conversions + dnorm + relay-flag reset
    prep_kernel<<<6931, 256>>>(input, w1_w, w2_w, d_w, p_inh, p_w1h, p_w2h, p_invnd, p_flags);

    // 2) GEMM1 (mish) fused with p_w transpose
    gemm1_tsplit<<<1024 + 4096, 256, SMEM_GEMM>>>(p_inh, p_w1h, p_xh, w1_b, p_w, p_pwT);

    // 3) depthwise conv (+*T, +d_b, *p_g) fused with pnorm
    dwconv_pnorm<<<4096, 256>>>(p_xh, p_yh, d_w, d_g, d_b, p_g, p_invnd, p_pwT, p_invnp);

    // 4) GEMM2 -> GEMM3 relay (single launch)
    gemm23<<<1024 + 384, 256, SMEM_GEMM>>>(p_yh, p_pwT, p_zh, p_invnp, p_b,
                                           p_w2h, out, w2_b, input, p_flags);
}

// round 14
// speedup vs baseline: 1.1991x; 1.0500x over previous
#include <cuda_runtime.h>
#include <cuda_fp16.h>
#include <stdint.h>
#include <math.h>

// Problem constants
#define BATCH 16
#define TT    1024
#define DIN   384
#define H1C   1024
#define H2C   1024
#define KW    9

// ---------------- scratch (device globals) -----------------------------------
__device__ __align__(128) __half g_inh[BATCH * TT * DIN];     // fp16 input   [b][t][384]
__device__ __align__(128) __half g_w1h[H1C * DIN];            // fp16 w1      [c][384]
__device__ __align__(128) __half g_w2h[DIN * H2C];            // fp16 w2      [d][1024]
__device__ __align__(128) __half g_pwT[BATCH * H2C * H1C];    // fp16 p_w^T   [b][o][1024]
__device__ __align__(128) __half g_xh [BATCH * TT * H1C];     // mish out     [b][t][c]
__device__ __align__(128) __half g_yh [BATCH * TT * H1C];     // conv out     [b][t][c]
__device__ __align__(128) __half g_zh [BATCH * TT * H2C];     // pointwise    [b][t][o]
__device__ float g_invnd[BATCH * KW];
__device__ float g_invnp[BATCH * H2C];
__device__ int   g_flags[BATCH * 16];                         // relay flags (b, 64-row tile)

// ---------------- helpers ----------------------------------------------------
__device__ __forceinline__ float mish_f(float v) {
    float sp = fmaxf(v, 0.f) + log1pf(expf(-fabsf(v)));
    return v * tanhf(sp);
}

__device__ __forceinline__ unsigned smem_u32(const void* p) {
    unsigned a;
    asm("{ .reg .u64 t; cvta.to.shared.u64 t, %1; cvt.u32.u64 %0, t; }" : "=r"(a) : "l"(p));
    return a;
}

__device__ __forceinline__ void cp_async16(unsigned dst, const void* src) {
    asm volatile("cp.async.cg.shared.global [%0], [%1], 16;" :: "r"(dst), "l"(src));
}

__device__ __forceinline__ void ldsm_x4(unsigned* r, unsigned addr) {
    asm volatile("ldmatrix.sync.aligned.m8n8.x4.shared.b16 {%0,%1,%2,%3}, [%4];"
        : "=r"(r[0]), "=r"(r[1]), "=r"(r[2]), "=r"(r[3]) : "r"(addr));
}

__device__ __forceinline__ void mma16816(float* d, const unsigned* a, unsigned b0, unsigned b1) {
    asm volatile("mma.sync.aligned.m16n8k16.row.col.f32.f16.f16.f32 "
        "{%0,%1,%2,%3}, {%4,%5,%6,%7}, {%8,%9}, {%0,%1,%2,%3};"
        : "+f"(d[0]), "+f"(d[1]), "+f"(d[2]), "+f"(d[3])
        : "r"(a[0]), "r"(a[1]), "r"(a[2]), "r"(a[3]), "r"(b0), "r"(b1));
}

// ---------------- mma.sync fp16 GEMM body ------------------------------------
// 256 threads, 2x4 warps on 32x32 tiles (CTA 64x128), K-chunk 32, 4-stage ring.
// Target 3 CTAs/SM (24 warps) via small accumulators.
// MODE 1: C fp16 = mish(acc + aux1[n])
// MODE 2: C fp16 = acc*aux1[b,n] + aux2[b,n]
// MODE 3: C f32 = acc + aux1[n] + R[b][m][n]
#define PITCH   80   // bytes per 32-half smem row (64B data + 16B pad)
#define NSTAGE  4
#define OPSTRA  (64 * PITCH)             // 5120: A region (64 rows) per stage
#define STSTR   (OPSTRA + 128 * PITCH)   // 15360 per stage (A 64 + B 128 rows)
#define SMEM_GEMM (NSTAGE * STSTR)       // 61440

template <int MODE>
__device__ __forceinline__ void gemm_body(
    int m0, int n0, int b,
    const __half* __restrict__ A, long long sA,
    const __half* __restrict__ B, long long sB,
    void* __restrict__ Cv, long long sC,
    int Ks, int ldc,
    const float* __restrict__ aux1, int a1s,
    const float* __restrict__ aux2, int a2s,
    const float* __restrict__ R,
    unsigned char* dynsm) {
    const int tid = threadIdx.x;
    const int wid = tid >> 5, lane = tid & 31;
    const int wm = wid & 1, wn = wid >> 1;   // 2 x 4 warp grid, 32x32 tiles

    const char* Ab = (const char*)(A + (long long)b * sA);
    const char* Bb = (const char*)(B + (long long)b * sB);
    const long long rowb = (long long)Ks * 2;   // fp16 row bytes

    // cp.async geometry:
    //   A: thread t -> row t/4 (0..63), 16B at (t&3)*16
    //   B: thread t -> row t/2 (0..127), 2x16B at (t&1)*32
    const char* Agp = Ab + (long long)(m0 + (tid >> 2)) * rowb + (tid & 3) * 16;
    const char* Bgp = Bb + (long long)(n0 + (tid >> 1)) * rowb + (tid & 1) * 32;
    const unsigned smBase = smem_u32(dynsm);
    const unsigned AsD = smBase + (unsigned)((tid >> 2) * PITCH + (tid & 3) * 16);
    const unsigned BsD = smBase + OPSTRA + (unsigned)((tid >> 1) * PITCH + (tid & 1) * 32);

    const int nch = Ks >> 5;

    float acc[2][4][4];
#pragma unroll
    for (int i = 0; i < 2; i++)
#pragma unroll
        for (int j = 0; j < 4; j++)
#pragma unroll
            for (int r = 0; r < 4; r++) acc[i][j][r] = 0.f;

    // ldmatrix lane offsets
    const unsigned aLane = (unsigned)((lane & 15) * PITCH + (lane >> 4) * 16);
    const unsigned bLane = (unsigned)(((lane & 8) + (lane & 7)) * PITCH + (lane >> 4) * 16);
    const unsigned baseA0 = smBase + (unsigned)(wm * 32 * PITCH);
    const unsigned baseB0 = smBase + OPSTRA + (unsigned)(wn * 32 * PITCH);

#define ISSUE(ic) do { \
    int _o = (ic) * 64; \
    unsigned _st = (unsigned)((ic) % NSTAGE) * STSTR; \
    cp_async16(AsD + _st, Agp + _o); \
    cp_async16(BsD + _st, Bgp + _o); \
    cp_async16(BsD + _st + 16, Bgp + _o + 16); \
    asm volatile("cp.async.commit_group;"); \
} while (0)

    // prologue: NSTAGE-1 groups always committed (empty when past end)
#pragma unroll
    for (int p = 0; p < NSTAGE - 1; p++) {
        if (p < nch) ISSUE(p);
        else asm volatile("cp.async.commit_group;");
    }

    for (int ic = 0; ic < nch; ic++) {
        asm volatile("cp.async.wait_group %0;" :: "n"(NSTAGE - 2));
        __syncthreads();
        // prefetch chunk ic+NSTAGE-1 into the slot last read at iteration ic-1
        if (ic + NSTAGE - 1 < nch) ISSUE(ic + NSTAGE - 1);
        else asm volatile("cp.async.commit_group;");

        unsigned st = (unsigned)(ic % NSTAGE) * STSTR;
        unsigned bA = baseA0 + st, bB = baseB0 + st;
#pragma unroll
        for (int ks = 0; ks < 2; ks++) {
            unsigned afr[2][4];
#pragma unroll
            for (int mi = 0; mi < 2; mi++)
                ldsm_x4(afr[mi], bA + (unsigned)(mi * 16 * PITCH) + (unsigned)(ks * 32) + aLane);
            unsigned bfr[4][2];
#pragma unroll
            for (int nj = 0; nj < 2; nj++) {
                unsigned r[4];
                ldsm_x4(r, bB + (unsigned)(nj * 16 * PITCH) + (unsigned)(ks * 32) + bLane);
                bfr[2 * nj][0] = r[0]; bfr[2 * nj][1] = r[2];
                bfr[2 * nj + 1][0] = r[1]; bfr[2 * nj + 1][1] = r[3];
            }
#pragma unroll
            for (int mi = 0; mi < 2; mi++)
#pragma unroll
                for (int ni = 0; ni < 4; ni++)
                    mma16816(acc[mi][ni], afr[mi], bfr[ni][0], bfr[ni][1]);
        }
    }
#undef ISSUE

    // epilogue: rows quad, quad+8; cols 2*(lane&3)+{0,1}
    const int quad = lane >> 2;
    const int col2 = (lane & 3) * 2;
#pragma unroll
    for (int mi = 0; mi < 2; mi++) {
#pragma unroll
        for (int half = 0; half < 2; half++) {
            int m = m0 + wm * 32 + mi * 16 + quad + half * 8;
#pragma unroll
            for (int ni = 0; ni < 4; ni++) {
                int n = n0 + wn * 32 + ni * 8 + col2;
                float v0 = acc[mi][ni][2 * half];
                float v1 = acc[mi][ni][2 * half + 1];
                if (MODE == 1) {
                    v0 = mish_f(v0 + aux1[n]);
                    v1 = mish_f(v1 + aux1[n + 1]);
                    __half* C = (__half*)Cv + (long long)b * sC + (long long)m * ldc + n;
                    *(__half2*)C = __floats2half2_rn(v0, v1);
                } else if (MODE == 2) {
                    v0 = v0 * aux1[b * a1s + n] + aux2[b * a2s + n];
                    v1 = v1 * aux1[b * a1s + n + 1] + aux2[b * a2s + n + 1];
                    __half* C = (__half*)Cv + (long long)b * sC + (long long)m * ldc + n;
                    *(__half2*)C = __floats2half2_rn(v0, v1);
                } else {
                    long long off = (long long)b * sC + (long long)m * ldc + n;
                    v0 = v0 + aux1[n] + R[off];
                    v1 = v1 + aux1[n + 1] + R[off + 1];
                    *(float2*)((float*)Cv + off) = make_float2(v0, v1);
                }
            }
        }
    }
}

// ---------------- prep: cvt input/w1/w2 + dnorm + flag reset, one launch -----
// blocks: [0,6144) input cvt | [6144,6528) w1 | [6528,6912) w2 | [6912,6930) dnorm
//         | 6930: zero relay flags
__global__ void prep_kernel(const float* __restrict__ input, const float* __restrict__ w1_w,
                            const float* __restrict__ w2_w, const float* __restrict__ d_w,
                            __half* __restrict__ inh, __half* __restrict__ w1h,
                            __half* __restrict__ w2h, float* __restrict__ invnd,
                            int* __restrict__ flags) {
    int bx = blockIdx.x;
    int tid = threadIdx.x;
    if (bx < 6912) {
        const float4* src;
        uint2* dst;
        long long i;
        if (bx < 6144) {
            src = (const float4*)input; dst = (uint2*)inh;
            i = (long long)bx * 256 + tid;
        } else if (bx < 6528) {
            src = (const float4*)w1_w; dst = (uint2*)w1h;
            i = (long long)(bx - 6144) * 256 + tid;
        } else {
            src = (const float4*)w2_w; dst = (uint2*)w2h;
            i = (long long)(bx - 6528) * 256 + tid;
        }
        float4 v = src[i];
        __half2 a = __floats2half2_rn(v.x, v.y);
        __half2 b = __floats2half2_rn(v.z, v.w);
        dst[i] = make_uint2(*(unsigned*)&a, *(unsigned*)&b);
    } else if (bx < 6930) {
        // dnorm: warp per (b,k), 18 blocks x 8 warps = 144
        int w = (bx - 6912) * 8 + (tid >> 5);
        int lane = tid & 31;
        int b = w / KW, k = w - KW * b;
        float s = 0.f;
#pragma unroll 8
        for (int c = lane; c < H1C; c += 32) {
            float v = d_w[((long long)b * H1C + c) * KW + k];
            s += v * v;
        }
#pragma unroll
        for (int o = 16; o > 0; o >>= 1) s += __shfl_xor_sync(0xffffffffu, s, o);
        if (lane == 0) invnd[b * KW + k] = 1.f / fmaxf(sqrtf(s), 1e-12f);
    } else {
        if (tid < BATCH * 16) flags[tid] = 0;
    }
}

// ---------------- fused GEMM1 + p_w transpose --------------------------------
// blocks [0,2048): GEMM1 64x128 tiles | [2048,6144): tsplit 64x64 tiles
__global__ void __launch_bounds__(256, 3)
gemm1_tsplit(const __half* __restrict__ A, const __half* __restrict__ Bw,
             __half* __restrict__ X, const float* __restrict__ w1b,
             const float* __restrict__ pw, __half* __restrict__ pwT) {
    extern __shared__ __align__(16) unsigned char dynsm[];
    int bx = blockIdx.x;
    int tid = threadIdx.x;
    if (bx < 2048) {
        int b = bx >> 7;
        int rem = bx & 127;
        int m0 = (rem >> 3) * 64, n0 = (rem & 7) * 128;
        gemm_body<1>(m0, n0, b, A, (long long)TT * DIN, Bw, 0,
                     (void*)X, (long long)TT * H1C, DIN, H1C,
                     w1b, 0, nullptr, 0, nullptr, dynsm);
    } else {
        // tsplit: [b][c][o] f32 -> [b][o][c] fp16, 64x64 tiles
        int lin = bx - 2048;
        int b = lin >> 8;
        int rem = lin & 255;
        int c0 = (rem >> 4) * 64;
        int o0 = (rem & 15) * 64;
        float(*tile)[65] = (float(*)[65])dynsm;
        const float* I = pw + (long long)b * H1C * H2C;
        __half* O = pwT + (long long)b * H2C * H1C;
        int tx = tid & 15, ty = tid >> 4;  // 16 x 16
#pragma unroll
        for (int it = 0; it < 4; it++) {
            int r = ty + it * 16;
            float4 v = *(const float4*)(I + (long long)(c0 + r) * H2C + o0 + tx * 4);
            tile[r][tx * 4] = v.x;
            tile[r][tx * 4 + 1] = v.y;
            tile[r][tx * 4 + 2] = v.z;
            tile[r][tx * 4 + 3] = v.w;
        }
        __syncthreads();
        int wid = tid >> 5, lane = tid & 31;
#pragma unroll
        for (int o = wid; o < 64; o += 8) {
            __half2 v = __floats2half2_rn(tile[2 * lane][o], tile[2 * lane + 1][o]);
            *(__half2*)(O + (long long)(o0 + o) * H1C + c0 + 2 * lane) = v;
        }
    }
}

// ---------------- fused depthwise conv + pnorm -------------------------------
// blocks [0,2048): dwconv (sliding-window) | [2048,4096): pnorm
__global__ void dwconv_pnorm(const __half* __restrict__ x, __half* __restrict__ y,
                             const float* __restrict__ d_w, const float* __restrict__ d_g,
                             const float* __restrict__ d_b, const float* __restrict__ p_g,
                             const float* __restrict__ invnd,
                             const __half* __restrict__ pwT, float* __restrict__ invnp) {
    int bx = blockIdx.x;
    int tid = threadIdx.x;  // 256
    if (bx < 2048) {
        int b = bx >> 7;
        int rem = bx & 127;
        int c0 = (rem & 7) * 128;
        int t0 = (rem >> 3) * 64;
        __shared__ float xs[72][128];
        __shared__ float ws[KW][128];
        __shared__ float sdb[128], spg[128];
        const __half* xb = x + (long long)b * TT * H1C;
        for (int i = tid; i < 72 * 64; i += 256) {
            int r = i >> 6, c2 = i & 63;
            int t = t0 - 4 + r;
            float2 v = make_float2(0.f, 0.f);
            if (t >= 0 && t < TT)
                v = __half22float2(*(const __half2*)(xb + (long long)t * H1C + c0 + 2 * c2));
            xs[r][2 * c2] = v.x;
            xs[r][2 * c2 + 1] = v.y;
        }
        if (tid < 128) {
            int c = c0 + tid;
            float g = d_g[b * H1C + c];
#pragma unroll
            for (int k = 0; k < KW; k++)
                ws[k][tid] = d_w[((long long)b * H1C + c) * KW + k] * invnd[b * KW + k] * g;
            sdb[tid] = d_b[b * H1C + c];
            spg[tid] = p_g[b * H1C + c];
        }
        __syncthreads();
        int tx = tid & 127, ty = tid >> 7;
        float w9[KW];
#pragma unroll
        for (int k = 0; k < KW; k++) w9[k] = ws[k][tx];
        float db = sdb[tx], pg = spg[tx];
        __half* yb = y + (long long)b * TT * H1C;
        float win[KW];
#pragma unroll
        for (int k = 0; k < KW - 1; k++) win[k] = xs[ty * 32 + k][tx];
#pragma unroll
        for (int q = 0; q < 32; q++) {
            int tt = ty * 32 + q;
            win[KW - 1] = xs[tt + KW - 1][tx];
            float a = 0.f;
#pragma unroll
            for (int k = 0; k < KW; k++) a = fmaf(win[k], w9[k], a);
            float v = (a * (float)TT + db) * pg;
            yb[(long long)(t0 + tt) * H1C + c0 + tx] = __float2half(v);
#pragma unroll
            for (int k = 0; k < KW - 1; k++) win[k] = win[k + 1];
        }
    } else {
        int row = (bx - 2048) * 8 + (tid >> 5);
        int lane = tid & 31;
        const __half2* p = (const __half2*)(pwT + (long long)row * H1C);
        float s = 0.f;
#pragma unroll 4
        for (int j = lane; j < H1C / 2; j += 32) {
            float2 v = __half22float2(p[j]);
            s += v.x * v.x + v.y * v.y;
        }
#pragma unroll
        for (int o = 16; o > 0; o >>= 1) s += __shfl_xor_sync(0xffffffffu, s, o);
        if (lane == 0) invnp[row] = 1.f / fmaxf(sqrtf(s), 1e-12f);
    }
}

// ---------------- fused GEMM2 -> GEMM3 relay ---------------------------------
// bids [0,2048): GEMM2 64x128 tiles (arrive flag[b*16+my] when z tile stored)
// bids [2048,2816): GEMM3 64x128 tiles (spin until flag[b*16+my]==8, then run)
__global__ void __launch_bounds__(256, 3)
gemm23(const __half* __restrict__ y, const __half* __restrict__ pwT,
       __half* __restrict__ z, const float* __restrict__ invnp,
       const float* __restrict__ pb,
       const __half* __restrict__ w2h, float* __restrict__ out,
       const float* __restrict__ w2b, const float* __restrict__ resid,
       int* __restrict__ flags) {
    extern __shared__ __align__(16) unsigned char dynsm[];
    int bid = blockIdx.x;
    int tid = threadIdx.x;
    if (bid < 2048) {
        int b = bid >> 7;
        int rem = bid & 127;
        int my = rem >> 3, nx = rem & 7;
        gemm_body<2>(my * 64, nx * 128, b,
                     y, (long long)TT * H1C, pwT, (long long)H2C * H1C,
                     (void*)z, (long long)TT * H2C, H1C, H2C,
                     invnp, H2C, pb, H2C, nullptr, dynsm);
        __syncthreads();
        if (tid == 0) {
            __threadfence();
            atomicAdd(&flags[b * 16 + my], 1);
        }
    } else {
        int lin = bid - 2048;         // 0..767
        int b = lin / 48;
        int rem = lin - b * 48;
        int my = rem / 3, dx = rem - my * 3;
        if (tid == 0) {
            volatile int* f = &flags[b * 16 + my];
            while (*f < 8) {}
        }
        __syncthreads();
        gemm_body<3>(my * 64, dx * 128, b,
                     z, (long long)TT * H2C, w2h, 0,
                     (void*)out, (long long)TT * DIN, H2C, DIN,
                     w2b, 0, nullptr, 0, resid, dynsm);
    }
}

// ---------------- launch ------------------------------------------------------
extern "C" void kernel_launch(void* const* d_in, const int* in_sizes, int n_in,
                              void* d_out, int out_size) {
    const float* input = (const float*)d_in[0];
    const float* d_w   = (const float*)d_in[1];
    const float* d_g   = (const float*)d_in[2];
    const float* d_b   = (const float*)d_in[3];
    const float* p_w   = (const float*)d_in[4];
    const float* p_g   = (const float*)d_in[5];
    const float* p_b   = (const float*)d_in[6];
    const float* w1_w  = (const float*)d_in[7];
    const float* w1_b  = (const float*)d_in[8];
    const float* w2_w  = (const float*)d_in[9];
    const float* w2_b  = (const float*)d_in[10];
    float* out = (float*)d_out;
    (void)in_sizes; (void)n_in; (void)out_size;

    __half *p_inh, *p_w1h, *p_w2h, *p_pwT, *p_xh, *p_yh, *p_zh;
    float *p_invnd, *p_invnp;
    int* p_flags;
    cudaGetSymbolAddress((void**)&p_inh, g_inh);
    cudaGetSymbolAddress((void**)&p_w1h, g_w1h);
    cudaGetSymbolAddress((void**)&p_w2h, g_w2h);
    cudaGetSymbolAddress((void**)&p_pwT, g_pwT);
    cudaGetSymbolAddress((void**)&p_xh, g_xh);
    cudaGetSymbolAddress((void**)&p_yh, g_yh);
    cudaGetSymbolAddress((void**)&p_zh, g_zh);
    cudaGetSymbolAddress((void**)&p_invnd, g_invnd);
    cudaGetSymbolAddress((void**)&p_invnp, g_invnp);
    cudaGetSymbolAddress((void**)&p_flags, g_flags);

    // opt-in to 60KB dynamic smem (idempotent)
    cudaFuncSetAttribute(gemm1_tsplit, cudaFuncAttributeMaxDynamicSharedMemorySize, SMEM_GEMM);
    cudaFuncSetAttribute(gemm23, cudaFuncAttributeMaxDynamicSharedMemorySize, SMEM_GEMM);

    // 1) prep: all fp16 conversions + dnorm + relay-flag reset
    prep_kernel<<<6931, 256>>>(input, w1_w, w2_w, d_w, p_inh, p_w1h, p_w2h, p_invnd, p_flags);

    // 2) GEMM1 (mish) fused with p_w transpose
    gemm1_tsplit<<<2048 + 4096, 256, SMEM_GEMM>>>(p_inh, p_w1h, p_xh, w1_b, p_w, p_pwT);

    // 3) depthwise conv (+*T, +d_b, *p_g) fused with pnorm
    dwconv_pnorm<<<4096, 256>>>(p_xh, p_yh, d_w, d_g, d_b, p_g, p_invnd, p_pwT, p_invnp);

    // 4) GEMM2 -> GEMM3 relay (single launch)
    gemm23<<<2048 + 768, 256, SMEM_GEMM>>>(p_yh, p_pwT, p_zh, p_invnp, p_b,
                                           p_w2h, out, w2_b, input, p_flags);
}